// round 12
// baseline (speedup 1.0000x reference)
#include <cuda_runtime.h>
#include <math.h>

// ---------------------------------------------------------------------------
// BigReimplementationPathIntegrator: conv encoder -> h0, then 100-step GRU.
// Inputs (metadata order):
//  0 images[128,3,72,72]  1 actions[128,100,2]
//  2 cw1[64,3,5,5] 3 cb1[64] 4 cw2[64,64,3,3] 5 cb2[64] 6 cw3[64,64,3,3] 7 cb3[64]
//  8 fw1[1024,1024] 9 fb1[1024] 10 fw2[512,1024] 11 fb2[512] 12 fw3[512,512] 13 fb3[512]
//  14 w_ih[1536,2] 15 w_hh[1536,512] 16 b_ih[1536] 17 b_hh[1536]
// Output: out[128,100,512] then hT[128,512]  (6,619,136 floats)
//
// Launch plan (3-launch encoder so the GRU is launch #3 and gets ncu'd):
//  0 conv1 (+flag reset)   1 conv2+conv3 fused   2 fc chain (3 GEMMs)   3 GRU
// ---------------------------------------------------------------------------

#define NB 128
#define NT 100
#define HID 512
#define OUT_HT_OFF (128 * 100 * 512)

// scratch (device globals: no allocation allowed)
__device__ float g_x1[128 * 64 * 24 * 24];
__device__ float g_x3[128 * 1024];
__device__ float g_f1[128 * 1024];
__device__ float g_f2[128 * 512];
// h double buffer, quad-transposed layout: buffer p, float index
//   p*65536 + (k>>2)*512 + b*4 + (k&3)   == float4 [kq][b=0..127]
__device__ float g_hbuf[2 * 128 * 512];
// per-CTA step flags, 128B apart (32 u32 stride) to avoid line sharing
__device__ unsigned int g_flags[128 * 32];
__device__ unsigned int g_fcctr[4];

__device__ __forceinline__ unsigned ld_acquire(const unsigned* p) {
    unsigned v;
    asm volatile("ld.acquire.gpu.u32 %0, [%1];" : "=r"(v) : "l"(p) : "memory");
    return v;
}
__device__ __forceinline__ void st_release(unsigned* p, unsigned v) {
    asm volatile("st.release.gpu.u32 [%0], %1;" :: "l"(p), "r"(v) : "memory");
}

// ---------------- conv1: [128,3,72,72] -> [128,64,24,24], k5 s3 p2, relu ----
__global__ void __launch_bounds__(576, 1)
conv1_kernel(const float* __restrict__ img,
             const float* __restrict__ w,
             const float* __restrict__ bias) {
    extern __shared__ float sm[];
    float* s_img = sm;               // 3*74*74 padded image
    float* s_w   = sm + 3 * 74 * 74; // 64*75 weights
    int b = blockIdx.x, tid = threadIdx.x;  // 576 threads (24x24 outputs)
    // reset GRU flags + fc counters each run (graph-replay safe)
    if (b == 0) {
        if (tid < 128) g_flags[tid * 32] = 0u;
        if (tid < 4)   g_fcctr[tid] = 0u;
    }
    for (int i = tid; i < 3 * 74 * 74; i += 576) s_img[i] = 0.f;
    __syncthreads();
    for (int i = tid; i < 3 * 72 * 72; i += 576) {
        int ic = i / (72 * 72); int rem = i - ic * 72 * 72;
        int r = rem / 72, c = rem - r * 72;
        s_img[(ic * 74 + r + 2) * 74 + c + 2] = img[((b * 3 + ic) * 72 + r) * 72 + c];
    }
    for (int i = tid; i < 64 * 75; i += 576) s_w[i] = w[i];
    __syncthreads();
    int oy = tid / 24, ox = tid - oy * 24;
    int by = oy * 3, bx = ox * 3;
    for (int oc = 0; oc < 64; oc += 4) {
        float a0 = bias[oc], a1 = bias[oc + 1], a2 = bias[oc + 2], a3 = bias[oc + 3];
        const float* w0 = s_w + oc * 75;
        #pragma unroll
        for (int ic = 0; ic < 3; ic++) {
            #pragma unroll
            for (int ky = 0; ky < 5; ky++) {
                const float* ip = s_img + (ic * 74 + by + ky) * 74 + bx;
                const float* wp = w0 + ic * 25 + ky * 5;
                #pragma unroll
                for (int kx = 0; kx < 5; kx++) {
                    float v = ip[kx];
                    a0 += wp[kx] * v;
                    a1 += wp[75 + kx] * v;
                    a2 += wp[150 + kx] * v;
                    a3 += wp[225 + kx] * v;
                }
            }
        }
        int o = (b * 64 + oc) * 576 + tid;
        g_x1[o]        = fmaxf(a0, 0.f);
        g_x1[o + 576]  = fmaxf(a1, 0.f);
        g_x1[o + 1152] = fmaxf(a2, 0.f);
        g_x1[o + 1728] = fmaxf(a3, 0.f);
    }
}

// ---------------- conv2+conv3 fused (per-batch): x1 -> x2(smem) -> x3 -------
// conv2: [64,24,24]->[64,9,9] k3 s3 p2 relu ; conv3: ->[64,4,4] k3 s3 p2 relu
// smem layout (floats): A[11664] | C[5184] | B[36928]   total 53776 = 215104 B
__global__ void __launch_bounds__(256, 1)
conv23_kernel(const float* __restrict__ w2, const float* __restrict__ b2,
              const float* __restrict__ w3, const float* __restrict__ b3) {
    extern __shared__ float sm[];
    float* A = sm;             // conv2 input chunk (16*27*27), later conv3 padded in
    float* C = sm + 11664;     // x2 buffer 64*81
    float* B = sm + 16848;     // conv2 w (64*145), later conv3 w (64*577)
    int b = blockIdx.x, tid = threadIdx.x;

    // ---- phase A: conv2 ----
    {
        int oc = tid >> 2, spl = tid & 3;
        float acc[21];
        int off[21];
        #pragma unroll
        for (int si = 0; si < 21; si++) {
            int s = spl + si * 4;
            if (s < 81) { int oyy = s / 9, oxx = s - oyy * 9; off[si] = oyy * 81 + oxx * 3; }
            else off[si] = 0;
            acc[si] = 0.f;
        }
        for (int c = 0; c < 4; c++) {
            int ic0 = c * 16;
            __syncthreads();
            for (int i = tid; i < 16 * 27 * 27; i += 256) {
                int ic = i / 729; int rem = i - ic * 729;
                int iy = rem / 27, ix = rem - iy * 27;
                float v = 0.f;
                if (iy >= 2 && iy < 26 && ix >= 2 && ix < 26)
                    v = g_x1[((b * 64 + ic0 + ic) * 24 + (iy - 2)) * 24 + (ix - 2)];
                A[i] = v;
            }
            for (int i = tid; i < 64 * 144; i += 256) {
                int o = i / 144, rem = i - o * 144;
                B[o * 145 + rem] = w2[(o * 64 + ic0) * 9 + rem];
            }
            __syncthreads();
            const float* wrow = B + oc * 145;
            #pragma unroll 2
            for (int ic = 0; ic < 16; ic++) {
                const float* inb = A + ic * 729;
                #pragma unroll
                for (int kk = 0; kk < 9; kk++) {
                    int ky = kk / 3, kx = kk - ky * 3;
                    float wv = wrow[ic * 9 + kk];
                    int d = ky * 27 + kx;
                    #pragma unroll
                    for (int si = 0; si < 21; si++)
                        acc[si] += wv * inb[off[si] + d];
                }
            }
        }
        float bb = b2[oc];
        #pragma unroll
        for (int si = 0; si < 21; si++) {
            int s = spl + si * 4;
            if (s < 81) C[oc * 81 + s] = fmaxf(acc[si] + bb, 0.f);
        }
    }
    __syncthreads();   // C complete; B/A free to overwrite

    // ---- phase B: conv3 ----
    for (int i = tid; i < 64 * 576; i += 256) {
        int o = i / 576, rem = i - o * 576;
        B[o * 577 + rem] = w3[i];
    }
    for (int i = tid; i < 64 * 144; i += 256) {
        int ic = i / 144, rem = i - ic * 144;
        int iy = rem / 12, ix = rem - iy * 12;
        float v = 0.f;
        if (iy >= 2 && iy < 11 && ix >= 2 && ix < 11)
            v = C[ic * 81 + (iy - 2) * 9 + (ix - 2)];
        A[i] = v;
    }
    __syncthreads();
    int sp = tid & 15, ocl = tid >> 4;
    int oyy = sp >> 2, oxx = sp & 3;
    int base = (oyy * 3) * 12 + oxx * 3;
    float acc3[4];
    #pragma unroll
    for (int i = 0; i < 4; i++) acc3[i] = b3[ocl + 16 * i];
    #pragma unroll 4
    for (int ic = 0; ic < 64; ic++) {
        const float* inb = A + ic * 144 + base;
        #pragma unroll
        for (int kk = 0; kk < 9; kk++) {
            int ky = kk / 3, kx = kk - ky * 3;
            float v = inb[ky * 12 + kx];
            #pragma unroll
            for (int i = 0; i < 4; i++)
                acc3[i] += B[(ocl + 16 * i) * 577 + ic * 9 + kk] * v;
        }
    }
    #pragma unroll
    for (int i = 0; i < 4; i++) {
        int oc = ocl + 16 * i;
        g_x3[b * 1024 + oc * 16 + sp] = fmaxf(acc3[i], 0.f);
    }
}

// ---------------- fc chain: 3 GEMMs in one launch (grid 128, 1 wave) --------
__device__ __forceinline__ void fc_tile(const float* __restrict__ A,
                                        const float* __restrict__ W,
                                        const float* __restrict__ bias,
                                        float* __restrict__ C,
                                        int K, int N, int doRelu, int mode,
                                        int n0, int m0, int tid,
                                        float (*sA)[33], float (*sW)[33]) {
    int tx = tid & 15, ty = tid >> 4;
    float c00 = 0.f, c01 = 0.f, c10 = 0.f, c11 = 0.f;
    for (int k0 = 0; k0 < K; k0 += 32) {
        __syncthreads();
        for (int i = tid; i < 1024; i += 256) {
            int r = i >> 5, cc = i & 31;
            sA[r][cc] = A[(m0 + r) * K + k0 + cc];
            sW[r][cc] = W[(n0 + r) * K + k0 + cc];
        }
        __syncthreads();
        #pragma unroll
        for (int kk = 0; kk < 32; kk++) {
            float a0 = sA[ty * 2][kk],   a1 = sA[ty * 2 + 1][kk];
            float b0 = sW[tx * 2][kk],   b1 = sW[tx * 2 + 1][kk];
            c00 += a0 * b0; c01 += a0 * b1; c10 += a1 * b0; c11 += a1 * b1;
        }
    }
    int m = m0 + ty * 2, n = n0 + tx * 2;
    float vv[4] = {c00, c01, c10, c11};
    #pragma unroll
    for (int q = 0; q < 4; q++) {
        int mm = m + (q >> 1), nn = n + (q & 1);
        float v = vv[q] + bias[nn];
        if (doRelu) v = fmaxf(v, 0.f);
        if (mode == 0) C[mm * N + nn] = v;
        else           C[(nn >> 2) * 512 + mm * 4 + (nn & 3)] = v;
    }
}

__device__ __forceinline__ void fc_barrier(int p, int tid) {
    __threadfence();
    __syncthreads();
    if (tid == 0) {
        atomicAdd(&g_fcctr[p], 1u);
        while (ld_acquire(&g_fcctr[p]) < 128u) { }
    }
    __syncthreads();
}

__global__ void __launch_bounds__(256, 1)
fc_chain_kernel(const float* __restrict__ fw1, const float* __restrict__ fb1,
                const float* __restrict__ fw2, const float* __restrict__ fb2,
                const float* __restrict__ fw3, const float* __restrict__ fb3) {
    __shared__ float sA[32][33];
    __shared__ float sW[32][33];
    int blk = blockIdx.x, tid = threadIdx.x;

    // fc1: [128,1024] @ fw1[1024,1024]^T, relu -> g_f1  (32 n-tiles x 4 m-tiles)
    fc_tile(g_x3, fw1, fb1, g_f1, 1024, 1024, 1, 0,
            (blk & 31) * 32, (blk >> 5) * 32, tid, sA, sW);
    fc_barrier(0, tid);
    // fc2: [128,1024] @ fw2[512,1024]^T, relu -> g_f2   (16 x 4 = 64 blocks)
    if (blk < 64)
        fc_tile(g_f1, fw2, fb2, g_f2, 1024, 512, 1, 0,
                (blk & 15) * 32, (blk >> 4) * 32, tid, sA, sW);
    fc_barrier(1, tid);
    // fc3: [128,512] @ fw3[512,512]^T -> h0 quad-transposed into g_hbuf[0]
    if (blk < 64)
        fc_tile(g_f2, fw3, fb3, g_hbuf, 512, 512, 0, 1,
                (blk & 15) * 32, (blk >> 4) * 32, tid, sA, sW);
}

// ---------------- GRU: persistent, 128 CTAs x 512 thr, packed f32x2 FMA -----
__device__ __forceinline__ unsigned long long ffma2(unsigned long long a,
                                                    unsigned long long b,
                                                    unsigned long long c) {
    unsigned long long d;
    asm("fma.rn.f32x2 %0, %1, %2, %3;" : "=l"(d) : "l"(a), "l"(b), "l"(c));
    return d;
}
__device__ __forceinline__ float redu2(unsigned long long v) {
    float lo, hi;
    asm("mov.b64 {%0, %1}, %2;" : "=f"(lo), "=f"(hi) : "l"(v));
    return lo + hi;
}

// smem (bytes): s_h 65536 | s_w 98304 | s_act 25600 | s_out 2048  = 191488
__global__ void __launch_bounds__(512, 1)
gru_kernel(const float* __restrict__ actions,
           const float* __restrict__ w_ih,
           const float* __restrict__ w_hh,
           const float* __restrict__ b_ih,
           const float* __restrict__ b_hh,
           float* __restrict__ out) {
    extern __shared__ char smraw[];
    ulonglong2* s_h = (ulonglong2*)smraw;              // [kq=128][lb=32] float4
    ulonglong2* s_w = s_h + 128 * 32;                  // [row=48][kq=128] float4
    float* s_act = (float*)(s_w + 48 * 128);           // [lb=32][t=100][2]
    float* s_out = s_act + 32 * 200;                   // [lb=32][il=16]

    int tid = threadIdx.x;
    int lane = tid & 31, wi = tid >> 5;                // 16 warps: 1 i per warp
    int bb = blockIdx.x >> 5, ib = blockIdx.x & 31;    // 4 b-blocks x 32 i-blocks
    int b0 = bb * 32, i0 = ib * 16;
    int i_out = i0 + wi;                               // this warp's output dim
    int b = b0 + lane;

    // load w_hh slice: row = g*16 + il  <->  j = g*512 + i0 + il
    for (int i = tid; i < 48 * 128; i += 512) {
        int row = i >> 7, kq = i & 127;
        int j = (row >> 4) * 512 + i0 + (row & 15);
        s_w[row * 128 + kq] =
            *reinterpret_cast<const ulonglong2*>(w_hh + j * 512 + kq * 4);
    }
    // preload actions for this b-block
    for (int i = tid; i < 32 * 200; i += 512) s_act[i] = actions[b0 * 200 + i];

    // per-thread gate params (uniform across lanes -> broadcast LDG)
    float wia[3], wib[3], bih[3], bhh[3];
    #pragma unroll
    for (int g = 0; g < 3; g++) {
        int j = g * 512 + i_out;
        wia[g] = w_ih[j * 2 + 0];
        wib[g] = w_ih[j * 2 + 1];
        bih[g] = b_ih[j];
        bhh[g] = b_hh[j];
    }
    __syncthreads();

    const ulonglong2* wp0 = s_w + (0 * 16 + wi) * 128;   // gate r row
    const ulonglong2* wp1 = s_w + (1 * 16 + wi) * 128;   // gate z row
    const ulonglong2* wp2 = s_w + (2 * 16 + wi) * 128;   // gate n row

    unsigned* myflag = g_flags + blockIdx.x * 32;
    const float4* hb4 = (const float4*)g_hbuf;
    float4* out4 = (float4*)out;

    for (int t = 0; t < NT; t++) {
        int rp = t & 1, wp = rp ^ 1;
        if (t > 0) {
            if (tid < 32) {
                const unsigned* fp = g_flags + (bb * 32 + tid) * 32;
                while (ld_acquire(fp) < (unsigned)t) { }
            }
            __syncthreads();
        }
        // load h tile (quad-transposed global -> [kq][lb] smem)
        {
            const float4* src4 = hb4 + rp * 16384;
            #pragma unroll
            for (int i = 0; i < 8; i++) {
                int idx = tid + i * 512;
                int kq = idx >> 5, lb = idx & 31;
                float4 v = __ldcg(src4 + kq * 128 + b0 + lb);
                ((float4*)s_h)[kq * 32 + lb] = v;
            }
        }
        __syncthreads();

        // gh dot products: 3 gates x 1 i per thread, packed f32x2 FMA
        ulonglong2 a0 = {0ull, 0ull}, a1g = {0ull, 0ull}, a2 = {0ull, 0ull};
        #pragma unroll 8
        for (int kq = 0; kq < 128; kq++) {
            ulonglong2 h = s_h[kq * 32 + lane];
            ulonglong2 w;
            w = wp0[kq]; a0.x  = ffma2(h.x, w.x, a0.x);  a0.y  = ffma2(h.y, w.y, a0.y);
            w = wp1[kq]; a1g.x = ffma2(h.x, w.x, a1g.x); a1g.y = ffma2(h.y, w.y, a1g.y);
            w = wp2[kq]; a2.x  = ffma2(h.x, w.x, a2.x);  a2.y  = ffma2(h.y, w.y, a2.y);
        }

        float aa = s_act[lane * 200 + t * 2];
        float ab = s_act[lane * 200 + t * 2 + 1];
        float ghr = redu2(a0.x)  + redu2(a0.y)  + bhh[0];
        float ghz = redu2(a1g.x) + redu2(a1g.y) + bhh[1];
        float ghn = redu2(a2.x)  + redu2(a2.y)  + bhh[2];
        float gir = fmaf(ab, wib[0], fmaf(aa, wia[0], bih[0]));
        float giz = fmaf(ab, wib[1], fmaf(aa, wia[1], bih[1]));
        float gin = fmaf(ab, wib[2], fmaf(aa, wia[2], bih[2]));
        float r = 1.f / (1.f + expf(-(gir + ghr)));
        float z = 1.f / (1.f + expf(-(giz + ghz)));
        float n = tanhf(gin + r * ghn);
        float hc = ((const float*)s_h)[(i_out >> 2) * 128 + lane * 4 + (i_out & 3)];
        float hy = n + z * (hc - n);

        // stage for coalesced stores
        s_out[lane * 16 + wi] = hy;
        __syncthreads();

        // critical path first: h double buffer (4 x 512B rows), fence, release
        if (tid < 128) {
            int kql = tid >> 5, bq = tid & 31;
            const float* sp = s_out + bq * 16 + kql * 4;
            float4 v = {sp[0], sp[1], sp[2], sp[3]};
            float4* d = (float4*)g_hbuf + wp * 16384 + ((i0 >> 2) + kql) * 128 + b0 + bq;
            __stcg(d, v);
            __threadfence();
        }
        __syncthreads();
        if (tid == 0) st_release(myflag, (unsigned)(t + 1));

        // off critical path: sequence output (+ final hT), coalesced float4
        if (tid >= 128 && tid < 256) {
            int tt = tid - 128;
            int bq = tt >> 2, seg = tt & 3;
            const float* sp = s_out + bq * 16 + seg * 4;
            float4 v = {sp[0], sp[1], sp[2], sp[3]};
            out4[((b0 + bq) * NT + t) * 128 + (i0 >> 2) + seg] = v;
        }
        if (t == NT - 1 && tid >= 256 && tid < 384) {
            int tt = tid - 256;
            int bq = tt >> 2, seg = tt & 3;
            const float* sp = s_out + bq * 16 + seg * 4;
            float4 v = {sp[0], sp[1], sp[2], sp[3]};
            out4[(OUT_HT_OFF >> 2) + (b0 + bq) * 128 + (i0 >> 2) + seg] = v;
        }
        // next iteration's two __syncthreads (flag wait + h-load) protect
        // s_out/s_h reuse; no extra barrier needed here.
    }
}

// ---------------------------------------------------------------------------
extern "C" void kernel_launch(void* const* d_in, const int* in_sizes, int n_in,
                              void* d_out, int out_size) {
    const float* images  = (const float*)d_in[0];
    const float* actions = (const float*)d_in[1];
    const float* cw1 = (const float*)d_in[2];
    const float* cb1 = (const float*)d_in[3];
    const float* cw2 = (const float*)d_in[4];
    const float* cb2 = (const float*)d_in[5];
    const float* cw3 = (const float*)d_in[6];
    const float* cb3 = (const float*)d_in[7];
    const float* fw1 = (const float*)d_in[8];
    const float* fb1 = (const float*)d_in[9];
    const float* fw2 = (const float*)d_in[10];
    const float* fb2 = (const float*)d_in[11];
    const float* fw3 = (const float*)d_in[12];
    const float* fb3 = (const float*)d_in[13];
    const float* w_ih = (const float*)d_in[14];
    const float* w_hh = (const float*)d_in[15];
    const float* b_ih = (const float*)d_in[16];
    const float* b_hh = (const float*)d_in[17];
    float* out = (float*)d_out;

    const int SM1  = (3 * 74 * 74 + 64 * 75) * 4;   // 84912
    const int SM23 = 53776 * 4;                     // 215104
    const int SMG  = 128 * 32 * 16 + 48 * 128 * 16 + 32 * 200 * 4 + 32 * 16 * 4; // 191488

    cudaFuncSetAttribute(conv1_kernel,  cudaFuncAttributeMaxDynamicSharedMemorySize, SM1);
    cudaFuncSetAttribute(conv23_kernel, cudaFuncAttributeMaxDynamicSharedMemorySize, SM23);
    cudaFuncSetAttribute(gru_kernel,    cudaFuncAttributeMaxDynamicSharedMemorySize, SMG);

    conv1_kernel<<<128, 576, SM1>>>(images, cw1, cb1);
    conv23_kernel<<<128, 256, SM23>>>(cw2, cb2, cw3, cb3);
    fc_chain_kernel<<<128, 256>>>(fw1, fb1, fw2, fb2, fw3, fb3);
    gru_kernel<<<128, 512, SMG>>>(actions, w_ih, w_hh, b_ih, b_hh, out);
}